// round 8
// baseline (speedup 1.0000x reference)
#include <cuda_runtime.h>
#include <cstdint>

#define G        25
#define KIN      15
#define KOUT     3
#define XDIM     (G * KIN)        // 375
#define ODIM     (G * KOUT)       // 75

#define ROWS_PER_TILE  16
#define THREADS        384
#define STAGES         3
#define TILE_FLOATS    (ROWS_PER_TILE * XDIM)       // 6000
#define TILE_F4        (TILE_FLOATS / 4)            // 1500
#define SMEM_BYTES     (STAGES * TILE_FLOATS * 4)   // 72000
#define GRID_CTAS      444                           // 3 per SM * 148

__device__ __forceinline__ void cp_async16(void* smem_dst, const void* gmem_src) {
    uint32_t s = (uint32_t)__cvta_generic_to_shared(smem_dst);
    asm volatile("cp.async.cg.shared.global [%0], [%1], 16;\n" :: "r"(s), "l"(gmem_src));
}
__device__ __forceinline__ void cp_async_commit() {
    asm volatile("cp.async.commit_group;\n" ::: "memory");
}
__device__ __forceinline__ void cp_async_wait1() {
    asm volatile("cp.async.wait_group 1;\n" ::: "memory");
}

__global__ __launch_bounds__(THREADS, 3)
void mlp_rsna4_kernel(const float* __restrict__ x,
                      const float* __restrict__ W,
                      const int*   __restrict__ k_idx,
                      const int*   __restrict__ v_idx,
                      float* __restrict__ out,
                      int ntiles)
{
    extern __shared__ float sx[];    // STAGES * 6000 floats = 72000 B

    const int tid  = threadIdx.x;
    const int wrp  = tid >> 5;
    const int lane = tid & 31;
    const bool active = (lane < G);
    const int g      = lane;        // group owned by this lane
    const int o_role = wrp >> 2;    // 0..2 : which of the 3 outputs
    const int rslot  = wrp & 3;     // 0..3 : row slot within tile
    const int grid   = (int)gridDim.x;

    // ---- Per-thread persistent state: one (g,o) pair ----
    float wreg[KIN];   // 15
    int   ki[KIN];     // 15
    int   vi_o = 0;
    if (active) {
        #pragma unroll
        for (int i = 0; i < KIN; i++)
            wreg[i] = W[(g * KOUT + o_role) * KIN + i];
        #pragma unroll
        for (int i = 0; i < KIN; i++) ki[i] = k_idx[g * KIN + i];
        vi_o = v_idx[g * KOUT + o_role];
    }

    // ---- Prologue: prefetch tiles t0, t0+grid into buffers 0,1 ----
    const int tile0 = blockIdx.x;
    #pragma unroll
    for (int p = 0; p < STAGES - 1; p++) {
        const int t = tile0 + p * grid;
        if (t < ntiles) {
            const float4* __restrict__ xin =
                (const float4*)(x + (long long)t * TILE_FLOATS);
            float* dst = sx + p * TILE_FLOATS;
            #pragma unroll
            for (int i = tid; i < TILE_F4; i += THREADS)
                ((float4*)dst)[0], cp_async16(dst + i * 4, xin + i);
        }
        cp_async_commit();
    }

    // ---- Main loop: ONE barrier per tile ----
    int s = 0;
    for (int tile = tile0; tile < ntiles; tile += grid) {
        cp_async_wait1();         // group for buffer s retired (1 still in flight)
        __syncthreads();          // publish sx[s]; fence prev compute before the
                                  // prefetch below overwrites its buffer

        // Prefetch tile+2*grid into the buffer computed LAST iteration
        {
            const int pf = tile + (STAGES - 1) * grid;
            if (pf < ntiles) {
                const float4* __restrict__ xin =
                    (const float4*)(x + (long long)pf * TILE_FLOATS);
                float* dst = sx + ((s + STAGES - 1) % STAGES) * TILE_FLOATS;
                #pragma unroll
                for (int i = tid; i < TILE_F4; i += THREADS)
                    cp_async16(dst + i * 4, xin + i);
            }
            cp_async_commit();    // keep group count in lockstep (may be empty)
        }

        // Compute: warp (o_role, rslot); 4 rows per warp; direct stores
        if (active) {
            const float* __restrict__ xbuf = sx + s * TILE_FLOATS;
            #pragma unroll
            for (int rr = 0; rr < ROWS_PER_TILE / 4; rr++) {
                const int r = rslot + rr * 4;
                const float* __restrict__ xr = xbuf + r * XDIM;

                float acc = 0.f;
                #pragma unroll
                for (int i = 0; i < KIN; i++)
                    acc = fmaf(xr[ki[i]], wreg[i], acc);  // stride-15: conflict-free

                out[((long long)tile * ROWS_PER_TILE + r) * ODIM + vi_o] = acc;
            }
        }

        s = (s + 1 == STAGES) ? 0 : s + 1;
    }
}

extern "C" void kernel_launch(void* const* d_in, const int* in_sizes, int n_in,
                              void* d_out, int out_size)
{
    const float* x     = (const float*)d_in[0];
    const float* W     = (const float*)d_in[1];
    const int*   k_idx = (const int*)d_in[2];
    const int*   v_idx = (const int*)d_in[3];
    float* out = (float*)d_out;

    const int b_rows = in_sizes[0] / XDIM;          // 262144
    const int ntiles = b_rows / ROWS_PER_TILE;      // 16384

    cudaFuncSetAttribute(mlp_rsna4_kernel,
                         cudaFuncAttributeMaxDynamicSharedMemorySize, SMEM_BYTES);

    int grid = GRID_CTAS;
    if (grid > ntiles) grid = ntiles;
    mlp_rsna4_kernel<<<grid, THREADS, SMEM_BYTES>>>(x, W, k_idx, v_idx, out, ntiles);
}

// round 11
// speedup vs baseline: 1.0264x; 1.0264x over previous
#include <cuda_runtime.h>
#include <cstdint>

#define G        25
#define KIN      15
#define KOUT     3
#define XDIM     (G * KIN)        // 375
#define ODIM     (G * KOUT)       // 75

#define ROWS_PER_TILE  16
#define THREADS        384
#define ROWS_PER_SLOT  (ROWS_PER_TILE / 4)         // 4 rows per warp
#define TILE_F4        (ROWS_PER_TILE * XDIM / 4)  // 1500 float4 per tile
#define OUT_F4         (ROWS_PER_TILE * ODIM / 4)  // 300 float4 per tile
#define GRID_CTAS      592                          // 4 per SM * 148

__device__ __forceinline__ void cp_async16(void* smem_dst, const void* gmem_src) {
    uint32_t s = (uint32_t)__cvta_generic_to_shared(smem_dst);
    asm volatile("cp.async.cg.shared.global [%0], [%1], 16;\n" :: "r"(s), "l"(gmem_src));
}
__device__ __forceinline__ void cp_async_commit() {
    asm volatile("cp.async.commit_group;\n" ::: "memory");
}
__device__ __forceinline__ void cp_async_wait1() {
    asm volatile("cp.async.wait_group 1;\n" ::: "memory");
}

__global__ __launch_bounds__(THREADS, 4)
void mlp_rsna4_kernel(const float* __restrict__ x,
                      const float* __restrict__ W,
                      const int*   __restrict__ k_idx,
                      const int*   __restrict__ v_idx,
                      float* __restrict__ out,
                      int ntiles)
{
    __shared__ float sx[2][ROWS_PER_TILE * XDIM];   // 48000 B
    __shared__ float sout[ROWS_PER_TILE * ODIM];    //  4800 B

    const int tid  = threadIdx.x;
    const int wrp  = tid >> 5;
    const int lane = tid & 31;
    const bool active = (lane < G);
    const int g      = lane;        // group owned by this lane
    const int o_role = wrp >> 2;    // 0..2 : which of the 3 outputs
    const int rslot  = wrp & 3;     // 0..3 : row slot within tile

    // ---- Per-thread persistent state: W row + gather base ----
    float wreg[KIN];       // 15 regs
    int   kbase = 0;       // 1 reg (replaces 15-entry ki[] when contiguous)
    bool  contig = true;
    int   vi_o = 0;
    if (active) {
        #pragma unroll
        for (int i = 0; i < KIN; i++)
            wreg[i] = W[(g * KOUT + o_role) * KIN + i];
        kbase = k_idx[g * KIN];
        #pragma unroll
        for (int i = 1; i < KIN; i++)
            contig = contig && (k_idx[g * KIN + i] == kbase + i);
        vi_o = v_idx[g * KOUT + o_role];
    }

    // ---- Prefetch first tile into buffer 0 ----
    int tile = blockIdx.x;
    int buf = 0;
    if (tile < ntiles) {
        const float4* __restrict__ xin =
            (const float4*)(x + (long long)tile * ROWS_PER_TILE * XDIM);
        #pragma unroll
        for (int i = tid; i < TILE_F4; i += THREADS)
            cp_async16(&sx[0][i * 4], xin + i);
    }
    cp_async_commit();

    // ---- Pipelined grid-stride loop (R7 skeleton) ----
    for (; tile < ntiles; tile += gridDim.x) {
        const int next = tile + gridDim.x;
        if (next < ntiles) {
            const float4* __restrict__ xin =
                (const float4*)(x + (long long)next * ROWS_PER_TILE * XDIM);
            #pragma unroll
            for (int i = tid; i < TILE_F4; i += THREADS)
                cp_async16(&sx[buf ^ 1][i * 4], xin + i);
        }
        cp_async_commit();        // next-tile group in flight
        cp_async_wait1();         // current tile complete
        __syncthreads();          // publish x; prior flush done

        if (active) {
            #pragma unroll
            for (int rr = 0; rr < ROWS_PER_SLOT; rr++) {
                const int r = rslot + rr * 4;
                const float* __restrict__ xr = sx[buf] + r * XDIM;

                float acc = 0.f;
                if (contig) {
                    // kbase + i folds into LDS immediate offsets; stride-15
                    // across lanes -> conflict-free
                    #pragma unroll
                    for (int i = 0; i < KIN; i++)
                        acc = fmaf(xr[kbase + i], wreg[i], acc);
                } else {
                    // General fallback (L1-resident index table)
                    #pragma unroll
                    for (int i = 0; i < KIN; i++)
                        acc = fmaf(xr[k_idx[g * KIN + i]], wreg[i], acc);
                }

                sout[r * ODIM + vi_o] = acc;   // stride-3: conflict-free
            }
        }

        __syncthreads();          // sout complete

        // Coalesced vectorized flush: 4800 B contiguous span
        {
            const float4* __restrict__ so4 = (const float4*)sout;
            float4* __restrict__ o4 =
                (float4*)(out + (long long)tile * ROWS_PER_TILE * ODIM);
            #pragma unroll
            for (int i = tid; i < OUT_F4; i += THREADS)
                o4[i] = so4[i];
        }

        __syncthreads();          // reads of sx[buf]/sout done before reuse
        buf ^= 1;
    }
}

extern "C" void kernel_launch(void* const* d_in, const int* in_sizes, int n_in,
                              void* d_out, int out_size)
{
    const float* x     = (const float*)d_in[0];
    const float* W     = (const float*)d_in[1];
    const int*   k_idx = (const int*)d_in[2];
    const int*   v_idx = (const int*)d_in[3];
    float* out = (float*)d_out;

    const int b_rows = in_sizes[0] / XDIM;          // 262144
    const int ntiles = b_rows / ROWS_PER_TILE;      // 16384

    int grid = GRID_CTAS;
    if (grid > ntiles) grid = ntiles;
    mlp_rsna4_kernel<<<grid, THREADS>>>(x, W, k_idx, v_idx, out, ntiles);
}

// round 12
// speedup vs baseline: 1.0272x; 1.0008x over previous
#include <cuda_runtime.h>
#include <cstdint>

#define G        25
#define KIN      15
#define KOUT     3
#define XDIM     (G * KIN)        // 375
#define ODIM     (G * KOUT)       // 75

#define ROWS_PER_TILE  16
#define THREADS        384
#define ROWS_PER_SLOT  (ROWS_PER_TILE / 4)         // 4 rows per warp
#define TILE_F4        (ROWS_PER_TILE * XDIM / 4)  // 1500 float4 per tile
#define OUT_F4         (ROWS_PER_TILE * ODIM / 4)  // 300 float4 per tile
#define GRID_CTAS      444                          // 3 per SM * 148  (R7 sweet spot)

__device__ __forceinline__ void cp_async16(void* smem_dst, const void* gmem_src) {
    uint32_t s = (uint32_t)__cvta_generic_to_shared(smem_dst);
    asm volatile("cp.async.cg.shared.global [%0], [%1], 16;\n" :: "r"(s), "l"(gmem_src));
}
__device__ __forceinline__ void cp_async_commit() {
    asm volatile("cp.async.commit_group;\n" ::: "memory");
}
__device__ __forceinline__ void cp_async_wait1() {
    asm volatile("cp.async.wait_group 1;\n" ::: "memory");
}

__global__ __launch_bounds__(THREADS, 3)
void mlp_rsna4_kernel(const float* __restrict__ x,
                      const float* __restrict__ W,
                      const int*   __restrict__ k_idx,
                      const int*   __restrict__ v_idx,
                      float* __restrict__ out,
                      int ntiles)
{
    __shared__ float sx[2][ROWS_PER_TILE * XDIM];   // 48000 B
    __shared__ float sout[ROWS_PER_TILE * ODIM];    //  4800 B

    const int tid  = threadIdx.x;
    const int wrp  = tid >> 5;
    const int lane = tid & 31;
    const bool active = (lane < G);
    const int g      = lane;        // group owned by this lane
    const int o_role = wrp >> 2;    // 0..2 : which of the 3 outputs
    const int rslot  = wrp & 3;     // 0..3 : row slot within tile

    // ---- Per-thread persistent state: W row + gather base ----
    float wreg[KIN];       // 15 regs
    int   kbase = 0;       // 1 reg (replaces ki[15] when run is contiguous)
    bool  contig = true;
    int   vi_o = 0;
    if (active) {
        #pragma unroll
        for (int i = 0; i < KIN; i++)
            wreg[i] = W[(g * KOUT + o_role) * KIN + i];
        kbase = k_idx[g * KIN];
        #pragma unroll
        for (int i = 1; i < KIN; i++)
            contig = contig && (k_idx[g * KIN + i] == kbase + i);
        vi_o = v_idx[g * KOUT + o_role];
    }

    // ---- Prefetch first tile into buffer 0 ----
    int tile = blockIdx.x;
    int buf = 0;
    if (tile < ntiles) {
        const float4* __restrict__ xin =
            (const float4*)(x + (long long)tile * ROWS_PER_TILE * XDIM);
        #pragma unroll
        for (int i = tid; i < TILE_F4; i += THREADS)
            cp_async16(&sx[0][i * 4], xin + i);
    }
    cp_async_commit();

    // ---- Pipelined grid-stride loop (R7 skeleton, unchanged) ----
    for (; tile < ntiles; tile += gridDim.x) {
        const int next = tile + gridDim.x;
        if (next < ntiles) {
            const float4* __restrict__ xin =
                (const float4*)(x + (long long)next * ROWS_PER_TILE * XDIM);
            #pragma unroll
            for (int i = tid; i < TILE_F4; i += THREADS)
                cp_async16(&sx[buf ^ 1][i * 4], xin + i);
        }
        cp_async_commit();        // next-tile group in flight
        cp_async_wait1();         // current tile complete
        __syncthreads();          // publish x; prior flush done

        if (active) {
            #pragma unroll
            for (int rr = 0; rr < ROWS_PER_SLOT; rr++) {
                const int r = rslot + rr * 4;
                const float* __restrict__ xr = sx[buf] + r * XDIM;

                float acc = 0.f;
                if (contig) {
                    // kbase+i folds into LDS immediate offsets; stride-15
                    // across lanes -> conflict-free
                    #pragma unroll
                    for (int i = 0; i < KIN; i++)
                        acc = fmaf(xr[kbase + i], wreg[i], acc);
                } else {
                    // General fallback (L1-resident index table)
                    #pragma unroll
                    for (int i = 0; i < KIN; i++)
                        acc = fmaf(xr[k_idx[g * KIN + i]], wreg[i], acc);
                }

                sout[r * ODIM + vi_o] = acc;   // stride-3: conflict-free
            }
        }

        __syncthreads();          // sout complete

        // Coalesced vectorized flush, streaming (evict-first) stores:
        // output is write-once, keep it out of L2's read working set
        {
            const float4* __restrict__ so4 = (const float4*)sout;
            float4* __restrict__ o4 =
                (float4*)(out + (long long)tile * ROWS_PER_TILE * ODIM);
            #pragma unroll
            for (int i = tid; i < OUT_F4; i += THREADS)
                __stcs(o4 + i, so4[i]);
        }

        __syncthreads();          // reads of sx[buf]/sout done before reuse
        buf ^= 1;
    }
}

extern "C" void kernel_launch(void* const* d_in, const int* in_sizes, int n_in,
                              void* d_out, int out_size)
{
    const float* x     = (const float*)d_in[0];
    const float* W     = (const float*)d_in[1];
    const int*   k_idx = (const int*)d_in[2];
    const int*   v_idx = (const int*)d_in[3];
    float* out = (float*)d_out;

    const int b_rows = in_sizes[0] / XDIM;          // 262144
    const int ntiles = b_rows / ROWS_PER_TILE;      // 16384

    int grid = GRID_CTAS;
    if (grid > ntiles) grid = ntiles;
    mlp_rsna4_kernel<<<grid, THREADS>>>(x, W, k_idx, v_idx, out, ntiles);
}

// round 13
// speedup vs baseline: 1.1405x; 1.1103x over previous
#include <cuda_runtime.h>
#include <cstdint>

#define G        25
#define KIN      15
#define KOUT     3
#define XDIM     (G * KIN)        // 375
#define ODIM     (G * KOUT)       // 75

#define ROWS_PER_TILE  16
#define THREADS        384
#define ROWS_PER_SLOT  (ROWS_PER_TILE / 4)          // 4 rows per warp
#define TILE_FLOATS    (ROWS_PER_TILE * XDIM)       // 6000
#define TILE_BYTES_X   (TILE_FLOATS * 4)            // 24000 (16B-divisible)
#define OUT_F4         (ROWS_PER_TILE * ODIM / 4)   // 300 float4 per tile
#define GRID_CTAS      444                           // 3 per SM * 148

// ---- 1D TMA bulk copy: gmem -> smem, completion via mbarrier ----
__device__ __forceinline__ void tma_bulk_1d(uint32_t smem_dst, const void* gmem_src,
                                            uint32_t bytes, uint32_t mbar) {
    asm volatile(
        "cp.async.bulk.shared::cluster.global.mbarrier::complete_tx::bytes "
        "[%0], [%1], %2, [%3];"
        :: "r"(smem_dst), "l"(gmem_src), "r"(bytes), "r"(mbar) : "memory");
}
__device__ __forceinline__ void mbar_init(uint32_t mbar, uint32_t count) {
    asm volatile("mbarrier.init.shared.b64 [%0], %1;" :: "r"(mbar), "r"(count) : "memory");
}
__device__ __forceinline__ void mbar_expect_tx(uint32_t mbar, uint32_t bytes) {
    asm volatile("mbarrier.arrive.expect_tx.shared.b64 _, [%0], %1;"
                 :: "r"(mbar), "r"(bytes) : "memory");
}
__device__ __forceinline__ void mbar_wait(uint32_t mbar, uint32_t parity) {
    asm volatile(
        "{\n\t"
        ".reg .pred p;\n\t"
        "LAB_WAIT_%=:\n\t"
        "mbarrier.try_wait.parity.acquire.cta.shared::cta.b64 p, [%0], %1, 0x989680;\n\t"
        "@!p bra LAB_WAIT_%=;\n\t"
        "}"
        :: "r"(mbar), "r"(parity) : "memory");
}

__global__ __launch_bounds__(THREADS, 3)
void mlp_rsna4_kernel(const float* __restrict__ x,
                      const float* __restrict__ W,
                      const int*   __restrict__ k_idx,
                      const int*   __restrict__ v_idx,
                      float* __restrict__ out,
                      int ntiles)
{
    __shared__ float sx[2][TILE_FLOATS];             // 48000 B
    __shared__ float sout[ROWS_PER_TILE * ODIM];     //  4800 B
    __shared__ __align__(8) unsigned long long mbar_storage[2];

    const int tid  = threadIdx.x;
    const int wrp  = tid >> 5;
    const int lane = tid & 31;
    const bool active = (lane < G);
    const int g      = lane;        // group owned by this lane
    const int o_role = wrp >> 2;    // 0..2 : which of the 3 outputs
    const int rslot  = wrp & 3;     // 0..3 : row slot within tile

    const uint32_t mbar0 = (uint32_t)__cvta_generic_to_shared(&mbar_storage[0]);
    const uint32_t mbar1 = (uint32_t)__cvta_generic_to_shared(&mbar_storage[1]);
    const uint32_t sx0   = (uint32_t)__cvta_generic_to_shared(&sx[0][0]);
    const uint32_t sx1   = (uint32_t)__cvta_generic_to_shared(&sx[1][0]);

    // ---- Per-thread persistent state: one (g,o) pair (exact R7 compute) ----
    float wreg[KIN];   // 15
    int   ki[KIN];     // 15
    int   vi_o = 0;
    if (active) {
        #pragma unroll
        for (int i = 0; i < KIN; i++)
            wreg[i] = W[(g * KOUT + o_role) * KIN + i];
        #pragma unroll
        for (int i = 0; i < KIN; i++) ki[i] = k_idx[g * KIN + i];
        vi_o = v_idx[g * KOUT + o_role];
    }

    // ---- Init mbarriers, then prefetch first tile into buffer 0 ----
    if (tid == 0) {
        mbar_init(mbar0, 1);
        mbar_init(mbar1, 1);
    }
    __syncthreads();   // barriers visible before any TMA targets them

    int tile = blockIdx.x;
    if (tid == 0 && tile < ntiles) {
        mbar_expect_tx(mbar0, TILE_BYTES_X);
        tma_bulk_1d(sx0, x + (long long)tile * TILE_FLOATS, TILE_BYTES_X, mbar0);
    }

    // ---- Pipelined grid-stride loop ----
    int it = 0;   // iteration counter; buf = it&1, parity for buf = (it>>1)&1
    for (; tile < ntiles; tile += gridDim.x, it++) {
        const int buf = it & 1;
        const uint32_t parity = (it >> 1) & 1;

        // Prefetch next tile into the other buffer (its readers finished
        // last iteration; fenced by the trailing __syncthreads).
        const int next = tile + gridDim.x;
        if (tid == 0 && next < ntiles) {
            const uint32_t mb  = buf ? mbar0 : mbar1;
            const uint32_t dst = buf ? sx0   : sx1;
            mbar_expect_tx(mb, TILE_BYTES_X);
            tma_bulk_1d(dst, x + (long long)next * TILE_FLOATS, TILE_BYTES_X, mb);
        }

        // Wait for current tile's TMA completion
        mbar_wait(buf ? mbar1 : mbar0, parity);

        if (active) {
            #pragma unroll
            for (int rr = 0; rr < ROWS_PER_SLOT; rr++) {
                const int r = rslot + rr * 4;
                const float* __restrict__ xr = sx[buf] + r * XDIM;

                float acc = 0.f;
                #pragma unroll
                for (int i = 0; i < KIN; i++)
                    acc = fmaf(xr[ki[i]], wreg[i], acc);   // stride-15: conflict-free

                sout[r * ODIM + vi_o] = acc;               // stride-3: conflict-free
            }
        }

        __syncthreads();          // sout complete

        // Coalesced vectorized flush: 4800 B contiguous span (plain stores)
        {
            const float4* __restrict__ so4 = (const float4*)sout;
            float4* __restrict__ o4 =
                (float4*)(out + (long long)tile * ROWS_PER_TILE * ODIM);
            #pragma unroll
            for (int i = tid; i < OUT_F4; i += THREADS)
                o4[i] = so4[i];
        }

        __syncthreads();          // all reads of sx[buf]/sout done before reuse
    }
}

extern "C" void kernel_launch(void* const* d_in, const int* in_sizes, int n_in,
                              void* d_out, int out_size)
{
    const float* x     = (const float*)d_in[0];
    const float* W     = (const float*)d_in[1];
    const int*   k_idx = (const int*)d_in[2];
    const int*   v_idx = (const int*)d_in[3];
    float* out = (float*)d_out;

    const int b_rows = in_sizes[0] / XDIM;          // 262144
    const int ntiles = b_rows / ROWS_PER_TILE;      // 16384

    int grid = GRID_CTAS;
    if (grid > ntiles) grid = ntiles;
    mlp_rsna4_kernel<<<grid, THREADS>>>(x, W, k_idx, v_idx, out, ntiles);
}